// round 7
// baseline (speedup 1.0000x reference)
#include <cuda_runtime.h>
#include <math.h>

// GPTClosedLoop: 128-step closed-loop rollout of a tiny GPT.
// B=32, T_H=128, NR=1, L=6, D=128, H=4, DH=32.
//
// KV-cache incremental decode, one CTA per batch element, per-layer KV cache
// in __device__ global scratch (L2-resident).
// Round 5: 1024 threads/CTA, deeper K-splits -> 1-2 load-latency waves per
// GEMV phase (critical-path latency fix).

#define BATCH    32
#define TH       128
#define DMODEL   128
#define NLAYER   6
#define NHEAD    4
#define DH       32
#define NTHREADS 1024

// K: [b][l][dim][token]  (token fastest -> coalesced logit reads)
// V: [b][l][token][dim]  (dim fastest   -> coalesced AV reads)
__device__ float g_k[BATCH * NLAYER * DMODEL * TH];
__device__ float g_v[BATCH * NLAYER * TH * DMODEL];

__device__ __forceinline__ void block_layernorm(
    const float* __restrict__ in, float* __restrict__ outb,
    const float* __restrict__ w, const float* __restrict__ b,
    float* wred, int tid)
{
    float v = (tid < 128) ? in[tid] : 0.f;
    float s = v;
    #pragma unroll
    for (int o = 16; o > 0; o >>= 1) s += __shfl_xor_sync(0xffffffffu, s, o);
    if ((tid & 31) == 0) wred[tid >> 5] = s;
    __syncthreads();
    float m = (wred[0] + wred[1] + wred[2] + wred[3]) * (1.f / 128.f);
    __syncthreads();
    float dv = (tid < 128) ? (v - m) : 0.f;
    float sq = dv * dv;
    #pragma unroll
    for (int o = 16; o > 0; o >>= 1) sq += __shfl_xor_sync(0xffffffffu, sq, o);
    if ((tid & 31) == 0) wred[tid >> 5] = sq;
    __syncthreads();
    float var = (wred[0] + wred[1] + wred[2] + wred[3]) * (1.f / 128.f);
    float rstd = rsqrtf(var + 1e-5f);
    if (tid < 128) outb[tid] = dv * rstd * w[tid] + b[tid];
    __syncthreads();
}

__global__ __launch_bounds__(NTHREADS, 1)
void gpt_rollout_kernel(
    const float* __restrict__ data,
    const float* __restrict__ r,
    const float* __restrict__ wte_w,  const float* __restrict__ wte_b,
    const float* __restrict__ wpe,
    const float* __restrict__ ln1_w,  const float* __restrict__ ln1_b,
    const float* __restrict__ ln2_w,  const float* __restrict__ ln2_b,
    const float* __restrict__ qkv_w,  const float* __restrict__ qkv_b,
    const float* __restrict__ proj_w, const float* __restrict__ proj_b,
    const float* __restrict__ fc_w,   const float* __restrict__ fc_b,
    const float* __restrict__ fc2_w,  const float* __restrict__ fc2_b,
    const float* __restrict__ lnf_w,  const float* __restrict__ lnf_b,
    const float* __restrict__ head_w, const float* __restrict__ head_b,
    float* __restrict__ out)
{
    __shared__ float xb[128], hb[128], qb[128], ob[128];
    __shared__ float att[512], gb[512];
    __shared__ float red[4096];          // K-split partials: red[seg*NCOL + col]
    __shared__ float wred[32], scal[2];

    const int b   = blockIdx.x;
    const int tid = threadIdx.x;

    const float p0 = data[b * 2 + 0];
    const float p1 = data[b * 2 + 1];

    if (tid == 0) { scal[0] = 0.f; scal[1] = 0.f; }   // s, u_prev
    __syncthreads();

    for (int i = 0; i < TH; i++) {
        const float s_cur  = scal[0];
        const float u_prev = scal[1];
        if (tid == 0) out[b * TH + i] = s_cur;        // Y[:, i] = s (pre-update)
        const float e = r[b * TH + i] - s_cur;        // e_i = r_i - s

        // token embedding
        if (tid < 128) {
            xb[tid] = e * wte_w[tid] + u_prev * wte_w[128 + tid]
                      + wte_b[tid] + wpe[i * 128 + tid];
        }
        __syncthreads();

        for (int l = 0; l < NLAYER; l++) {
            float* kbase = g_k + (size_t)(b * NLAYER + l) * DMODEL * TH;  // [dim][tok]
            float* vbase = g_v + (size_t)(b * NLAYER + l) * TH * DMODEL;  // [tok][dim]

            // ----- ln1 -----
            block_layernorm(xb, hb, ln1_w + l * 128, ln1_b + l * 128, wred, tid);

            // ----- qkv GEMV: 96 col-groups(x4) * 8 K-segs(16) = 768 threads -----
            if (tid < 768) {
                const int s = tid / 96, g = tid % 96;
                const float* W = qkv_w + l * (128 * 384) + (s * 16) * 384 + 4 * g;
                const float* hp = hb + s * 16;
                float ax = 0.f, ay = 0.f, az = 0.f, aw = 0.f;
                #pragma unroll 8
                for (int d = 0; d < 16; d++) {
                    float h = hp[d];
                    float4 w4 = *(const float4*)(W + d * 384);
                    ax += h * w4.x; ay += h * w4.y; az += h * w4.z; aw += h * w4.w;
                }
                *(float4*)(red + s * 384 + 4 * g) = make_float4(ax, ay, az, aw);
            }
            __syncthreads();
            if (tid < 384) {
                float acc = qkv_b[l * 384 + tid];
                #pragma unroll
                for (int s = 0; s < 8; s++) acc += red[s * 384 + tid];
                if (tid < 128)      qb[tid] = acc;
                else if (tid < 256) kbase[(tid - 128) * TH + i] = acc;
                else                vbase[i * DMODEL + (tid - 256)] = acc;
            }
            __syncthreads();   // K/V global writes visible block-wide

            // ----- attention logits + softmax (thread = (head, key j)),
            //       threads >= 512 duplicate heads harmlessly -----
            {
                const int hh = (tid >> 7) & 3;  // head 0..3
                const int j  = tid & 127;       // key position
                const bool valid = (j <= i);
                const float* kp = kbase + (hh * DH) * TH + j;
                float dot = 0.f;
                #pragma unroll
                for (int d = 0; d < DH; d += 4) {
                    float4 qv = *(const float4*)(qb + hh * DH + d);
                    dot += qv.x * kp[(d + 0) * TH] + qv.y * kp[(d + 1) * TH]
                         + qv.z * kp[(d + 2) * TH] + qv.w * kp[(d + 3) * TH];
                }
                float logit = valid ? dot * 0.17677669529663689f : -3.0e38f;

                float mx = logit;
                #pragma unroll
                for (int o = 16; o > 0; o >>= 1)
                    mx = fmaxf(mx, __shfl_xor_sync(0xffffffffu, mx, o));
                if ((tid & 31) == 0) wred[tid >> 5] = mx;
                __syncthreads();
                float hmax = fmaxf(fmaxf(wred[hh * 4 + 0], wred[hh * 4 + 1]),
                                   fmaxf(wred[hh * 4 + 2], wred[hh * 4 + 3]));
                __syncthreads();

                float p = valid ? expf(logit - hmax) : 0.f;
                float ssum = p;
                #pragma unroll
                for (int o = 16; o > 0; o >>= 1)
                    ssum += __shfl_xor_sync(0xffffffffu, ssum, o);
                if ((tid & 31) == 0) wred[tid >> 5] = ssum;
                __syncthreads();
                float hsum = wred[hh * 4 + 0] + wred[hh * 4 + 1]
                           + wred[hh * 4 + 2] + wred[hh * 4 + 3];
                if (tid < 512) att[hh * 128 + j] = p / hsum;
            }
            __syncthreads();

            // ----- o = att @ V : j-split x8 (thread = (jseg, dim)) -----
            {
                const int s = tid >> 7, dim = tid & 127;
                const float* vp = vbase + dim;
                const float* ap = att + (dim >> 5) * 128;
                const int j0 = s * 16;
                const int j1 = min(j0 + 16, i + 1);
                float a0 = 0.f, a1 = 0.f;
                int j = j0;
                #pragma unroll 4
                for (; j + 1 < j1; j += 2) {
                    a0 += ap[j]     * vp[(j)     * DMODEL];
                    a1 += ap[j + 1] * vp[(j + 1) * DMODEL];
                }
                if (j < j1) a0 += ap[j] * vp[j * DMODEL];
                red[s * 128 + dim] = a0 + a1;
            }
            __syncthreads();
            if (tid < 128) {
                float acc = 0.f;
                #pragma unroll
                for (int s = 0; s < 8; s++) acc += red[s * 128 + tid];
                ob[tid] = acc;
            }
            __syncthreads();

            // ----- proj: 32 col-groups(x4) * 32 K-segs(4) = 1024 thr, 4 loads -----
            {
                const int s = tid >> 5, g = tid & 31;
                const float* W = proj_w + l * (128 * 128) + (s * 4) * 128 + 4 * g;
                const float* op = ob + s * 4;
                float ax = 0.f, ay = 0.f, az = 0.f, aw = 0.f;
                #pragma unroll
                for (int d = 0; d < 4; d++) {
                    float o = op[d];
                    float4 w4 = *(const float4*)(W + d * 128);
                    ax += o * w4.x; ay += o * w4.y; az += o * w4.z; aw += o * w4.w;
                }
                *(float4*)(red + s * 128 + 4 * g) = make_float4(ax, ay, az, aw);
            }
            __syncthreads();
            if (tid < 128) {
                float acc = proj_b[l * 128 + tid];
                #pragma unroll
                for (int s = 0; s < 32; s++) acc += red[s * 128 + tid];
                xb[tid] += acc;
            }
            __syncthreads();

            // ----- ln2 -----
            block_layernorm(xb, hb, ln2_w + l * 128, ln2_b + l * 128, wred, tid);

            // ----- fc: 128 col-groups(x4) * 8 K-segs(16) = 1024 threads -----
            {
                const int s = tid >> 7, g = tid & 127;
                const float* W = fc_w + l * (128 * 512) + (s * 16) * 512 + 4 * g;
                const float* hp = hb + s * 16;
                float ax = 0.f, ay = 0.f, az = 0.f, aw = 0.f;
                #pragma unroll 8
                for (int d = 0; d < 16; d++) {
                    float h = hp[d];
                    float4 w4 = *(const float4*)(W + d * 512);
                    ax += h * w4.x; ay += h * w4.y; az += h * w4.z; aw += h * w4.w;
                }
                *(float4*)(red + s * 512 + 4 * g) = make_float4(ax, ay, az, aw);
            }
            __syncthreads();
            if (tid < 512) {
                float t = fc_b[l * 512 + tid];
                #pragma unroll
                for (int s = 0; s < 8; s++) t += red[s * 512 + tid];
                float inner = 0.7978845608028654f * (t + 0.044715f * t * t * t);
                gb[tid] = 0.5f * t * (1.f + tanhf(inner));
            }
            __syncthreads();

            // ----- fc2: 32 col-groups(x4) * 32 K-segs(16) = 1024 threads -----
            {
                const int s = tid >> 5, g = tid & 31;
                const float* W = fc2_w + l * (512 * 128) + (s * 16) * 128 + 4 * g;
                const float* gp = gb + s * 16;
                float ax = 0.f, ay = 0.f, az = 0.f, aw = 0.f;
                #pragma unroll 8
                for (int d = 0; d < 16; d++) {
                    float gv = gp[d];
                    float4 w4 = *(const float4*)(W + d * 128);
                    ax += gv * w4.x; ay += gv * w4.y; az += gv * w4.z; aw += gv * w4.w;
                }
                *(float4*)(red + s * 128 + 4 * g) = make_float4(ax, ay, az, aw);
            }
            __syncthreads();
            if (tid < 128) {
                float acc = fc2_b[l * 128 + tid];
                #pragma unroll
                for (int s = 0; s < 32; s++) acc += red[s * 128 + tid];
                xb[tid] += acc;
            }
            __syncthreads();
        } // layers

        // ----- final LN + head -> u_next; state update -----
        block_layernorm(xb, hb, lnf_w, lnf_b, wred, tid);
        {
            float part = (tid < 128) ? hb[tid] * head_w[tid] : 0.f;
            #pragma unroll
            for (int o = 16; o > 0; o >>= 1)
                part += __shfl_xor_sync(0xffffffffu, part, o);
            if ((tid & 31) == 0) wred[tid >> 5] = part;
            __syncthreads();
            if (tid == 0) {
                float u = wred[0] + wred[1] + wred[2] + wred[3] + head_b[0];
                float sn = s_cur + (-p0 * s_cur + p1 * tanhf(u));
                scal[0] = sn;   // s_{i+1}
                scal[1] = u;    // U[:, i+1]
            }
            __syncthreads();
        }
    } // steps
}

extern "C" void kernel_launch(void* const* d_in, const int* in_sizes, int n_in,
                              void* d_out, int out_size)
{
    (void)in_sizes; (void)n_in; (void)out_size;
    gpt_rollout_kernel<<<BATCH, NTHREADS>>>(
        (const float*)d_in[0],   // data
        (const float*)d_in[1],   // r
        (const float*)d_in[2],   // wte_w
        (const float*)d_in[3],   // wte_b
        (const float*)d_in[4],   // wpe
        (const float*)d_in[5],   // ln1_w
        (const float*)d_in[6],   // ln1_b
        (const float*)d_in[7],   // ln2_w
        (const float*)d_in[8],   // ln2_b
        (const float*)d_in[9],   // qkv_w
        (const float*)d_in[10],  // qkv_b
        (const float*)d_in[11],  // attn_proj_w
        (const float*)d_in[12],  // attn_proj_b
        (const float*)d_in[13],  // fc_w
        (const float*)d_in[14],  // fc_b
        (const float*)d_in[15],  // fc2_w
        (const float*)d_in[16],  // fc2_b
        (const float*)d_in[17],  // lnf_w
        (const float*)d_in[18],  // lnf_b
        (const float*)d_in[19],  // head_w
        (const float*)d_in[20],  // head_b
        (float*)d_out);
}

// round 8
// speedup vs baseline: 1.2437x; 1.2437x over previous
#include <cuda_runtime.h>
#include <cuda_fp16.h>
#include <math.h>

// GPTClosedLoop: 128-step closed-loop rollout of a tiny GPT.
// B=32, T_H=128, NR=1, L=6, D=128, H=4, DH=32.
//
// KV-cache incremental decode, one CTA per batch element, per-layer KV cache
// in __device__ global scratch (L2-resident).
// Round 7: fp16 weight staging (converted once per launch) -> every GEMV is a
// SINGLE fully-batched load wave at 512 threads / 128 regs. Fused 1-pass LN.

#define BATCH    32
#define TH       128
#define DMODEL   128
#define NLAYER   6
#define NHEAD    4
#define DH       32
#define NTHREADS 512

// KV cache: K [b][l][dim][token], V [b][l][token][dim]
__device__ float g_k[BATCH * NLAYER * DMODEL * TH];
__device__ float g_v[BATCH * NLAYER * TH * DMODEL];

// fp16 weight stages
__device__ __half g_qkv_h [NLAYER * 128 * 384];
__device__ __half g_proj_h[NLAYER * 128 * 128];
__device__ __half g_fc_h  [NLAYER * 128 * 512];
__device__ __half g_fc2_h [NLAYER * 512 * 128];

__global__ void cvt_qkv (const float* __restrict__ s){ int i = blockIdx.x*1024+threadIdx.x; if (i < NLAYER*128*384) g_qkv_h [i] = __float2half_rn(s[i]); }
__global__ void cvt_proj(const float* __restrict__ s){ int i = blockIdx.x*1024+threadIdx.x; if (i < NLAYER*128*128) g_proj_h[i] = __float2half_rn(s[i]); }
__global__ void cvt_fc  (const float* __restrict__ s){ int i = blockIdx.x*1024+threadIdx.x; if (i < NLAYER*128*512) g_fc_h  [i] = __float2half_rn(s[i]); }
__global__ void cvt_fc2 (const float* __restrict__ s){ int i = blockIdx.x*1024+threadIdx.x; if (i < NLAYER*512*128) g_fc2_h [i] = __float2half_rn(s[i]); }

// fused single-pass LN: 2 barriers
__device__ __forceinline__ void block_layernorm(
    const float* __restrict__ in, float* __restrict__ outb,
    const float* __restrict__ w, const float* __restrict__ b,
    float* wred, int tid)
{
    float v = (tid < 128) ? in[tid] : 0.f;
    float s1 = v, s2 = v * v;
    #pragma unroll
    for (int o = 16; o > 0; o >>= 1) {
        s1 += __shfl_xor_sync(0xffffffffu, s1, o);
        s2 += __shfl_xor_sync(0xffffffffu, s2, o);
    }
    if ((tid & 31) == 0) { wred[tid >> 5] = s1; wred[16 + (tid >> 5)] = s2; }
    __syncthreads();
    float m  = (wred[0] + wred[1] + wred[2] + wred[3]) * (1.f / 128.f);
    float ex2 = (wred[16] + wred[17] + wred[18] + wred[19]) * (1.f / 128.f);
    float var = ex2 - m * m;
    float rstd = rsqrtf(var + 1e-5f);
    if (tid < 128) outb[tid] = (v - m) * rstd * w[tid] + b[tid];
    __syncthreads();
}

__global__ __launch_bounds__(NTHREADS, 1)
void gpt_rollout_kernel(
    const float* __restrict__ data,
    const float* __restrict__ r,
    const float* __restrict__ wte_w,  const float* __restrict__ wte_b,
    const float* __restrict__ wpe,
    const float* __restrict__ ln1_w,  const float* __restrict__ ln1_b,
    const float* __restrict__ ln2_w,  const float* __restrict__ ln2_b,
    const float* __restrict__ qkv_b,
    const float* __restrict__ proj_b,
    const float* __restrict__ fc_b,
    const float* __restrict__ fc2_b,
    const float* __restrict__ lnf_w,  const float* __restrict__ lnf_b,
    const float* __restrict__ head_w, const float* __restrict__ head_b,
    float* __restrict__ out)
{
    __shared__ float xb[128], hb[128], qb[128], ob[128];
    __shared__ float att[512], gb[512];
    __shared__ float red[4096];
    __shared__ float wred[32], scal[2];

    const int b   = blockIdx.x;
    const int tid = threadIdx.x;

    const float p0 = data[b * 2 + 0];
    const float p1 = data[b * 2 + 1];

    if (tid == 0) { scal[0] = 0.f; scal[1] = 0.f; }   // s, u_prev
    __syncthreads();

    for (int i = 0; i < TH; i++) {
        const float s_cur  = scal[0];
        const float u_prev = scal[1];
        if (tid == 0) out[b * TH + i] = s_cur;        // Y[:, i] = s (pre-update)
        const float e = r[b * TH + i] - s_cur;        // e_i = r_i - s

        if (tid < 128) {
            xb[tid] = e * wte_w[tid] + u_prev * wte_w[128 + tid]
                      + wte_b[tid] + wpe[i * 128 + tid];
        }
        __syncthreads();

        for (int l = 0; l < NLAYER; l++) {
            float* kbase = g_k + (size_t)(b * NLAYER + l) * DMODEL * TH;
            float* vbase = g_v + (size_t)(b * NLAYER + l) * TH * DMODEL;

            // ----- ln1 -----
            block_layernorm(xb, hb, ln1_w + l * 128, ln1_b + l * 128, wred, tid);

            // ----- qkv: 48 col-groups(x8) * 8 K-segs(16) = 384 thr, 16 loads -----
            if (tid < 384) {
                const int s = tid / 48, g = tid % 48;
                const __half* W = g_qkv_h + l * (128 * 384) + (s * 16) * 384 + g * 8;
                const float* hp = hb + s * 16;
                float a0=0,a1=0,a2=0,a3=0,a4=0,a5=0,a6=0,a7=0;
                #pragma unroll
                for (int d = 0; d < 16; d++) {
                    float h = hp[d];
                    uint4 wv = *(const uint4*)(W + d * 384);
                    const __half2* h2 = reinterpret_cast<const __half2*>(&wv);
                    float2 f0 = __half22float2(h2[0]);
                    float2 f1 = __half22float2(h2[1]);
                    float2 f2 = __half22float2(h2[2]);
                    float2 f3 = __half22float2(h2[3]);
                    a0 += h*f0.x; a1 += h*f0.y; a2 += h*f1.x; a3 += h*f1.y;
                    a4 += h*f2.x; a5 += h*f2.y; a6 += h*f3.x; a7 += h*f3.y;
                }
                float4* rp = (float4*)(red + s * 384 + g * 8);
                rp[0] = make_float4(a0, a1, a2, a3);
                rp[1] = make_float4(a4, a5, a6, a7);
            }
            __syncthreads();
            if (tid < 384) {
                float acc = qkv_b[l * 384 + tid];
                #pragma unroll
                for (int s = 0; s < 8; s++) acc += red[s * 384 + tid];
                if (tid < 128)      qb[tid] = acc;
                else if (tid < 256) kbase[(tid - 128) * TH + i] = acc;
                else                vbase[i * DMODEL + (tid - 256)] = acc;
            }
            __syncthreads();

            // ----- attention logits + softmax (thread = (head, key j)) -----
            {
                const int hh = tid >> 7;        // head 0..3
                const int j  = tid & 127;       // key position
                const bool valid = (j <= i);
                const float* kp = kbase + (hh * DH) * TH + j;
                float dot = 0.f;
                #pragma unroll
                for (int d = 0; d < DH; d += 4) {
                    float4 qv = *(const float4*)(qb + hh * DH + d);
                    dot += qv.x * kp[(d + 0) * TH] + qv.y * kp[(d + 1) * TH]
                         + qv.z * kp[(d + 2) * TH] + qv.w * kp[(d + 3) * TH];
                }
                float logit = valid ? dot * 0.17677669529663689f : -3.0e38f;

                float mx = logit;
                #pragma unroll
                for (int o = 16; o > 0; o >>= 1)
                    mx = fmaxf(mx, __shfl_xor_sync(0xffffffffu, mx, o));
                if ((tid & 31) == 0) wred[tid >> 5] = mx;
                __syncthreads();
                float hmax = fmaxf(fmaxf(wred[hh * 4 + 0], wred[hh * 4 + 1]),
                                   fmaxf(wred[hh * 4 + 2], wred[hh * 4 + 3]));
                __syncthreads();

                float p = valid ? expf(logit - hmax) : 0.f;
                float ssum = p;
                #pragma unroll
                for (int o = 16; o > 0; o >>= 1)
                    ssum += __shfl_xor_sync(0xffffffffu, ssum, o);
                if ((tid & 31) == 0) wred[tid >> 5] = ssum;
                __syncthreads();
                float hsum = wred[hh * 4 + 0] + wred[hh * 4 + 1]
                           + wred[hh * 4 + 2] + wred[hh * 4 + 3];
                att[hh * 128 + j] = p / hsum;
            }
            __syncthreads();

            // ----- o = att @ V : j-split x4, 4 accumulators -----
            {
                const int s = tid >> 7, dim = tid & 127;
                const float* vp = vbase + dim;
                const float* ap = att + (dim >> 5) * 128;
                const int j0 = s * 32;
                const int j1 = min(j0 + 32, i + 1);
                float a0=0.f, a1=0.f, a2=0.f, a3=0.f;
                int j = j0;
                #pragma unroll 2
                for (; j + 3 < j1; j += 4) {
                    a0 += ap[j]     * vp[(j)     * DMODEL];
                    a1 += ap[j + 1] * vp[(j + 1) * DMODEL];
                    a2 += ap[j + 2] * vp[(j + 2) * DMODEL];
                    a3 += ap[j + 3] * vp[(j + 3) * DMODEL];
                }
                for (; j < j1; j++) a0 += ap[j] * vp[j * DMODEL];
                red[s * 128 + dim] = (a0 + a1) + (a2 + a3);
            }
            __syncthreads();
            if (tid < 128)
                ob[tid] = red[tid] + red[128 + tid] + red[256 + tid] + red[384 + tid];
            __syncthreads();

            // ----- proj: 16 col-groups(x8) * 32 K-segs(4) = 512 thr, 4 loads -----
            {
                const int s = tid >> 4, g = tid & 15;
                const __half* W = g_proj_h + l * (128 * 128) + (s * 4) * 128 + g * 8;
                const float* op = ob + s * 4;
                float a0=0,a1=0,a2=0,a3=0,a4=0,a5=0,a6=0,a7=0;
                #pragma unroll
                for (int d = 0; d < 4; d++) {
                    float o = op[d];
                    uint4 wv = *(const uint4*)(W + d * 128);
                    const __half2* h2 = reinterpret_cast<const __half2*>(&wv);
                    float2 f0 = __half22float2(h2[0]);
                    float2 f1 = __half22float2(h2[1]);
                    float2 f2 = __half22float2(h2[2]);
                    float2 f3 = __half22float2(h2[3]);
                    a0 += o*f0.x; a1 += o*f0.y; a2 += o*f1.x; a3 += o*f1.y;
                    a4 += o*f2.x; a5 += o*f2.y; a6 += o*f3.x; a7 += o*f3.y;
                }
                float4* rp = (float4*)(red + s * 128 + g * 8);
                rp[0] = make_float4(a0, a1, a2, a3);
                rp[1] = make_float4(a4, a5, a6, a7);
            }
            __syncthreads();
            if (tid < 128) {
                float acc = proj_b[l * 128 + tid];
                #pragma unroll
                for (int s = 0; s < 32; s++) acc += red[s * 128 + tid];
                xb[tid] += acc;
            }
            __syncthreads();

            // ----- ln2 -----
            block_layernorm(xb, hb, ln2_w + l * 128, ln2_b + l * 128, wred, tid);

            // ----- fc: 64 col-groups(x8) * 8 K-segs(16) = 512 thr, 16 loads -----
            {
                const int s = tid >> 6, g = tid & 63;
                const __half* W = g_fc_h + l * (128 * 512) + (s * 16) * 512 + g * 8;
                const float* hp = hb + s * 16;
                float a0=0,a1=0,a2=0,a3=0,a4=0,a5=0,a6=0,a7=0;
                #pragma unroll
                for (int d = 0; d < 16; d++) {
                    float h = hp[d];
                    uint4 wv = *(const uint4*)(W + d * 512);
                    const __half2* h2 = reinterpret_cast<const __half2*>(&wv);
                    float2 f0 = __half22float2(h2[0]);
                    float2 f1 = __half22float2(h2[1]);
                    float2 f2 = __half22float2(h2[2]);
                    float2 f3 = __half22float2(h2[3]);
                    a0 += h*f0.x; a1 += h*f0.y; a2 += h*f1.x; a3 += h*f1.y;
                    a4 += h*f2.x; a5 += h*f2.y; a6 += h*f3.x; a7 += h*f3.y;
                }
                float4* rp = (float4*)(red + s * 512 + g * 8);
                rp[0] = make_float4(a0, a1, a2, a3);
                rp[1] = make_float4(a4, a5, a6, a7);
            }
            __syncthreads();
            {
                float t = fc_b[l * 512 + tid];
                #pragma unroll
                for (int s = 0; s < 8; s++) t += red[s * 512 + tid];
                float inner = 0.7978845608028654f * (t + 0.044715f * t * t * t);
                gb[tid] = 0.5f * t * (1.f + tanhf(inner));
            }
            __syncthreads();

            // ----- fc2: 16 col-groups(x8) * 32 K-segs(16) = 512 thr, 16 loads -----
            {
                const int s = tid >> 4, g = tid & 15;
                const __half* W = g_fc2_h + l * (512 * 128) + (s * 16) * 128 + g * 8;
                const float* gp = gb + s * 16;
                float a0=0,a1=0,a2=0,a3=0,a4=0,a5=0,a6=0,a7=0;
                #pragma unroll
                for (int d = 0; d < 16; d++) {
                    float gv = gp[d];
                    uint4 wv = *(const uint4*)(W + d * 128);
                    const __half2* h2 = reinterpret_cast<const __half2*>(&wv);
                    float2 f0 = __half22float2(h2[0]);
                    float2 f1 = __half22float2(h2[1]);
                    float2 f2 = __half22float2(h2[2]);
                    float2 f3 = __half22float2(h2[3]);
                    a0 += gv*f0.x; a1 += gv*f0.y; a2 += gv*f1.x; a3 += gv*f1.y;
                    a4 += gv*f2.x; a5 += gv*f2.y; a6 += gv*f3.x; a7 += gv*f3.y;
                }
                float4* rp = (float4*)(red + s * 128 + g * 8);
                rp[0] = make_float4(a0, a1, a2, a3);
                rp[1] = make_float4(a4, a5, a6, a7);
            }
            __syncthreads();
            if (tid < 128) {
                float acc = fc2_b[l * 128 + tid];
                #pragma unroll
                for (int s = 0; s < 32; s++) acc += red[s * 128 + tid];
                xb[tid] += acc;
            }
            __syncthreads();
        } // layers

        // ----- final LN + head -> u_next; state update -----
        block_layernorm(xb, hb, lnf_w, lnf_b, wred, tid);
        {
            float part = (tid < 128) ? hb[tid] * head_w[tid] : 0.f;
            #pragma unroll
            for (int o = 16; o > 0; o >>= 1)
                part += __shfl_xor_sync(0xffffffffu, part, o);
            if ((tid & 31) == 0) wred[tid >> 5] = part;
            __syncthreads();
            if (tid == 0) {
                float u = wred[0] + wred[1] + wred[2] + wred[3] + head_b[0];
                float sn = s_cur + (-p0 * s_cur + p1 * tanhf(u));
                scal[0] = sn;   // s_{i+1}
                scal[1] = u;    // U[:, i+1]
            }
            __syncthreads();
        }
    } // steps
}

extern "C" void kernel_launch(void* const* d_in, const int* in_sizes, int n_in,
                              void* d_out, int out_size)
{
    (void)in_sizes; (void)n_in; (void)out_size;

    cvt_qkv <<<(NLAYER*128*384 + 1023)/1024, 1024>>>((const float*)d_in[9]);
    cvt_proj<<<(NLAYER*128*128 + 1023)/1024, 1024>>>((const float*)d_in[11]);
    cvt_fc  <<<(NLAYER*128*512 + 1023)/1024, 1024>>>((const float*)d_in[13]);
    cvt_fc2 <<<(NLAYER*512*128 + 1023)/1024, 1024>>>((const float*)d_in[15]);

    gpt_rollout_kernel<<<BATCH, NTHREADS>>>(
        (const float*)d_in[0],   // data
        (const float*)d_in[1],   // r
        (const float*)d_in[2],   // wte_w
        (const float*)d_in[3],   // wte_b
        (const float*)d_in[4],   // wpe
        (const float*)d_in[5],   // ln1_w
        (const float*)d_in[6],   // ln1_b
        (const float*)d_in[7],   // ln2_w
        (const float*)d_in[8],   // ln2_b
        (const float*)d_in[10],  // qkv_b
        (const float*)d_in[12],  // attn_proj_b
        (const float*)d_in[14],  // fc_b
        (const float*)d_in[16],  // fc2_b
        (const float*)d_in[17],  // lnf_w
        (const float*)d_in[18],  // lnf_b
        (const float*)d_in[19],  // head_w
        (const float*)d_in[20],  // head_b
        (float*)d_out);
}